// round 1
// baseline (speedup 1.0000x reference)
#include <cuda_runtime.h>

#define HEADS 4
#define DIM_HEAD 32
#define NPOS 4096
#define BATCH 4
#define CDIM 256
#define HIDDEN 128
#define SCALE 0.17677669529663687f  // 32^-0.5

// Scratch (allocation-free rule: __device__ globals)
__device__ __align__(16) float g_q[BATCH * HEADS * NPOS * DIM_HEAD];
__device__ __align__(16) float g_k[BATCH * HEADS * NPOS * DIM_HEAD];
__device__ __align__(16) float g_v[BATCH * HEADS * NPOS * DIM_HEAD];
__device__ __align__(16) float g_attn[BATCH * NPOS * HIDDEN];

// ---------------------------------------------------------------------------
// Kernel 1: QKV projection.  qkv[o][pos] = sum_c w_qkv[o][c] * x[b][c][pos]
// 64x64 output tile per block, K-tiles of 16. Scatter into per-head buffers.
// ---------------------------------------------------------------------------
__global__ __launch_bounds__(256) void qkv_kernel(const float* __restrict__ x,
                                                  const float* __restrict__ w) {
    __shared__ __align__(16) float Wt[16][68];
    __shared__ __align__(16) float Xt[16][68];
    const int b  = blockIdx.z;
    const int o0 = blockIdx.y * 64;
    const int p0 = blockIdx.x * 64;
    const int tid = threadIdx.x;
    const int ty = tid >> 4, tx = tid & 15;

    float acc[4][4] = {};

    for (int k0 = 0; k0 < CDIM; k0 += 16) {
        {   // W tile: 64 rows x 16 k  (transpose into Wt[k][o])
            int oo = tid >> 2, kq = tid & 3;
            float4 wv = *(const float4*)&w[(o0 + oo) * CDIM + k0 + kq * 4];
            Wt[kq * 4 + 0][oo] = wv.x;
            Wt[kq * 4 + 1][oo] = wv.y;
            Wt[kq * 4 + 2][oo] = wv.z;
            Wt[kq * 4 + 3][oo] = wv.w;
        }
        {   // X tile: 16 k x 64 pos (already k-major rows)
            int kk = tid >> 4, pq = tid & 15;
            float4 xv = *(const float4*)&x[((size_t)b * CDIM + k0 + kk) * NPOS + p0 + pq * 4];
            *(float4*)&Xt[kk][pq * 4] = xv;
        }
        __syncthreads();
        #pragma unroll
        for (int kk = 0; kk < 16; kk++) {
            float4 a  = *(float4*)&Wt[kk][ty * 4];
            float4 bv = *(float4*)&Xt[kk][tx * 4];
            float av[4] = {a.x, a.y, a.z, a.w};
            float bb[4] = {bv.x, bv.y, bv.z, bv.w};
            #pragma unroll
            for (int i = 0; i < 4; i++)
                #pragma unroll
                for (int j = 0; j < 4; j++) acc[i][j] += av[i] * bb[j];
        }
        __syncthreads();
    }

    // Scatter to q/k/v buffers laid out [b][head][pos][d]
    #pragma unroll
    for (int i = 0; i < 4; i++) {
        int o = o0 + ty * 4 + i;
        int part = o >> 7;          // 0=q 1=k 2=v
        int oc = o & 127;
        int head = oc >> 5, d = oc & 31;
        float* dst = (part == 0) ? g_q : (part == 1) ? g_k : g_v;
        float sc = (part == 0) ? SCALE : 1.0f;
        size_t base = (((size_t)b * HEADS + head) * NPOS) * DIM_HEAD + d;
        #pragma unroll
        for (int j = 0; j < 4; j++) {
            int pos = p0 + tx * 4 + j;
            dst[base + (size_t)pos * DIM_HEAD] = acc[i][j] * sc;
        }
    }
}

// ---------------------------------------------------------------------------
// Kernel 2: flash attention, one (b,head) pair x 64-query tile per block.
// 8 warps, each owns 8 query rows. Lane j owns output d-column j.
// ---------------------------------------------------------------------------
__global__ __launch_bounds__(256) void attn_kernel() {
    __shared__ __align__(16) float Qs[64][36];
    __shared__ __align__(16) float Ks[64][36];
    __shared__ __align__(16) float Vs[64][36];
    __shared__ __align__(16) float Ps[64][64];

    const int bh = blockIdx.y;
    const int q0 = blockIdx.x * 64;
    const int tid = threadIdx.x;
    const int warp = tid >> 5, lane = tid & 31;
    const int row0 = warp * 8;

    const float* Qg = g_q + (size_t)bh * NPOS * DIM_HEAD;
    const float* Kg = g_k + (size_t)bh * NPOS * DIM_HEAD;
    const float* Vg = g_v + (size_t)bh * NPOS * DIM_HEAD;

    // Load Q tile (64 x 32) -> Qs
    for (int e = tid; e < 512; e += 256) {
        int r = e >> 3, dq = (e & 7) * 4;
        *(float4*)&Qs[r][dq] = *(const float4*)&Qg[(size_t)(q0 + r) * DIM_HEAD + dq];
    }

    float m[8], l[8], o[8];
    #pragma unroll
    for (int r = 0; r < 8; r++) { m[r] = -1e30f; l[r] = 0.f; o[r] = 0.f; }

    const int c0 = lane, c1 = lane + 32;

    for (int t = 0; t < NPOS; t += 64) {
        __syncthreads();   // also covers first-use of Qs; protects Ks/Vs reuse
        for (int e = tid; e < 512; e += 256) {
            int r = e >> 3, dq = (e & 7) * 4;
            *(float4*)&Ks[r][dq] = *(const float4*)&Kg[(size_t)(t + r) * DIM_HEAD + dq];
            *(float4*)&Vs[r][dq] = *(const float4*)&Vg[(size_t)(t + r) * DIM_HEAD + dq];
        }
        __syncthreads();

        // S = Q K^T : each lane computes 8 rows x 2 key columns
        float s0[8] = {}, s1[8] = {};
        #pragma unroll
        for (int dd = 0; dd < 32; dd += 4) {
            float4 k0 = *(float4*)&Ks[c0][dd];
            float4 k1 = *(float4*)&Ks[c1][dd];
            #pragma unroll
            for (int r = 0; r < 8; r++) {
                float4 q = *(float4*)&Qs[row0 + r][dd];
                s0[r] += q.x * k0.x + q.y * k0.y + q.z * k0.z + q.w * k0.w;
                s1[r] += q.x * k1.x + q.y * k1.y + q.z * k1.z + q.w * k1.w;
            }
        }

        // online softmax per row (warp-wide reductions over 64 key cols)
        #pragma unroll
        for (int r = 0; r < 8; r++) {
            float mv = fmaxf(s0[r], s1[r]);
            #pragma unroll
            for (int off = 16; off; off >>= 1)
                mv = fmaxf(mv, __shfl_xor_sync(0xffffffffu, mv, off));
            float mt = fmaxf(m[r], mv);
            float alpha = __expf(m[r] - mt);
            float p0 = __expf(s0[r] - mt);
            float p1 = __expf(s1[r] - mt);
            float ps = p0 + p1;
            #pragma unroll
            for (int off = 16; off; off >>= 1)
                ps += __shfl_xor_sync(0xffffffffu, ps, off);
            l[r] = l[r] * alpha + ps;
            m[r] = mt;
            o[r] *= alpha;
            Ps[row0 + r][lane]      = p0;
            Ps[row0 + r][lane + 32] = p1;
        }
        __syncwarp();   // Ps rows are warp-private; make writes visible

        // O += P V : lane j accumulates column d=j over 64 keys
        #pragma unroll
        for (int jj = 0; jj < 64; jj += 4) {
            float v0 = Vs[jj + 0][lane];
            float v1 = Vs[jj + 1][lane];
            float v2 = Vs[jj + 2][lane];
            float v3 = Vs[jj + 3][lane];
            #pragma unroll
            for (int r = 0; r < 8; r++) {
                float4 p = *(float4*)&Ps[row0 + r][jj];
                o[r] += p.x * v0 + p.y * v1 + p.z * v2 + p.w * v3;
            }
        }
        __syncwarp();
    }

    // Write normalized output: g_attn[b][pos][head*32 + d]
    const int b = bh >> 2, head = bh & 3;
    #pragma unroll
    for (int r = 0; r < 8; r++) {
        int pos = q0 + row0 + r;
        g_attn[((size_t)b * NPOS + pos) * HIDDEN + head * 32 + lane] = o[r] / l[r];
    }
}

// ---------------------------------------------------------------------------
// Kernel 3: output projection + bias.
// y[b][o][pos] = sum_c w_out[o][c] * g_attn[b][pos][c] + b_out[o]
// ---------------------------------------------------------------------------
__global__ __launch_bounds__(256) void proj_kernel(const float* __restrict__ w,
                                                   const float* __restrict__ bias,
                                                   float* __restrict__ y) {
    __shared__ __align__(16) float Wt[16][68];
    __shared__ __align__(16) float Bt[16][68];
    const int b  = blockIdx.z;
    const int o0 = blockIdx.y * 64;
    const int p0 = blockIdx.x * 64;
    const int tid = threadIdx.x;
    const int ty = tid >> 4, tx = tid & 15;

    float acc[4][4] = {};

    for (int k0 = 0; k0 < HIDDEN; k0 += 16) {
        {
            int oo = tid >> 2, kq = tid & 3;
            float4 wv = *(const float4*)&w[(o0 + oo) * HIDDEN + k0 + kq * 4];
            Wt[kq * 4 + 0][oo] = wv.x;
            Wt[kq * 4 + 1][oo] = wv.y;
            Wt[kq * 4 + 2][oo] = wv.z;
            Wt[kq * 4 + 3][oo] = wv.w;
        }
        {
            int pp = tid >> 2, kq = tid & 3;
            float4 av = *(const float4*)&g_attn[((size_t)b * NPOS + p0 + pp) * HIDDEN + k0 + kq * 4];
            Bt[kq * 4 + 0][pp] = av.x;
            Bt[kq * 4 + 1][pp] = av.y;
            Bt[kq * 4 + 2][pp] = av.z;
            Bt[kq * 4 + 3][pp] = av.w;
        }
        __syncthreads();
        #pragma unroll
        for (int kk = 0; kk < 16; kk++) {
            float4 a  = *(float4*)&Wt[kk][ty * 4];
            float4 bv = *(float4*)&Bt[kk][tx * 4];
            float av[4] = {a.x, a.y, a.z, a.w};
            float bb[4] = {bv.x, bv.y, bv.z, bv.w};
            #pragma unroll
            for (int i = 0; i < 4; i++)
                #pragma unroll
                for (int j = 0; j < 4; j++) acc[i][j] += av[i] * bb[j];
        }
        __syncthreads();
    }

    #pragma unroll
    for (int i = 0; i < 4; i++) {
        int o = o0 + ty * 4 + i;
        float bb = bias[o];
        #pragma unroll
        for (int j = 0; j < 4; j++) {
            int pos = p0 + tx * 4 + j;
            y[((size_t)b * CDIM + o) * NPOS + pos] = acc[i][j] + bb;
        }
    }
}

// ---------------------------------------------------------------------------
extern "C" void kernel_launch(void* const* d_in, const int* in_sizes, int n_in,
                              void* d_out, int out_size) {
    const float* x     = (const float*)d_in[0];
    const float* w_qkv = (const float*)d_in[1];
    const float* w_out = (const float*)d_in[2];
    const float* b_out = (const float*)d_in[3];
    float* y = (float*)d_out;

    qkv_kernel<<<dim3(NPOS / 64, 384 / 64, BATCH), 256>>>(x, w_qkv);
    attn_kernel<<<dim3(NPOS / 64, BATCH * HEADS), 256>>>();
    proj_kernel<<<dim3(NPOS / 64, CDIM / 64, BATCH), 256>>>(w_out, b_out, y);
}

// round 3
// speedup vs baseline: 2.8101x; 2.8101x over previous
#include <cuda_runtime.h>
#include <cstdint>

#define HEADS 4
#define DIM_HEAD 32
#define NPOS 4096
#define BATCH 4
#define CDIM 256
#define HIDDEN 128
#define SCALE 0.17677669529663687f  // 32^-0.5

// Scratch (allocation-free rule: __device__ globals)
__device__ __align__(16) float g_q[BATCH * HEADS * NPOS * DIM_HEAD];
__device__ __align__(16) float g_k[BATCH * HEADS * NPOS * DIM_HEAD];
__device__ __align__(16) float g_v[BATCH * HEADS * NPOS * DIM_HEAD];
__device__ __align__(16) float g_attn[BATCH * NPOS * HIDDEN];

// ---------------------------------------------------------------------------
// tf32 helpers
// ---------------------------------------------------------------------------
__device__ __forceinline__ uint32_t f2tf32(float x) {
    uint32_t u;
    asm("cvt.rna.tf32.f32 %0, %1;" : "=r"(u) : "f"(x));
    return u;
}

__device__ __forceinline__ void mma_tf32(float (&c)[4],
                                         uint32_t a0, uint32_t a1, uint32_t a2, uint32_t a3,
                                         uint32_t b0, uint32_t b1) {
    asm volatile(
        "mma.sync.aligned.m16n8k8.row.col.f32.tf32.tf32.f32 "
        "{%0,%1,%2,%3},{%4,%5,%6,%7},{%8,%9},{%0,%1,%2,%3};\n"
        : "+f"(c[0]), "+f"(c[1]), "+f"(c[2]), "+f"(c[3])
        : "r"(a0), "r"(a1), "r"(a2), "r"(a3), "r"(b0), "r"(b1));
}

// ---------------------------------------------------------------------------
// Kernel 1: QKV projection.  qkv[o][pos] = sum_c w_qkv[o][c] * x[b][c][pos]
// ---------------------------------------------------------------------------
__global__ __launch_bounds__(256) void qkv_kernel(const float* __restrict__ x,
                                                  const float* __restrict__ w) {
    __shared__ __align__(16) float Wt[16][68];
    __shared__ __align__(16) float Xt[16][68];
    const int b  = blockIdx.z;
    const int o0 = blockIdx.y * 64;
    const int p0 = blockIdx.x * 64;
    const int tid = threadIdx.x;
    const int ty = tid >> 4, tx = tid & 15;

    float acc[4][4] = {};

    for (int k0 = 0; k0 < CDIM; k0 += 16) {
        {
            int oo = tid >> 2, kq = tid & 3;
            float4 wv = *(const float4*)&w[(o0 + oo) * CDIM + k0 + kq * 4];
            Wt[kq * 4 + 0][oo] = wv.x;
            Wt[kq * 4 + 1][oo] = wv.y;
            Wt[kq * 4 + 2][oo] = wv.z;
            Wt[kq * 4 + 3][oo] = wv.w;
        }
        {
            int kk = tid >> 4, pq = tid & 15;
            float4 xv = *(const float4*)&x[((size_t)b * CDIM + k0 + kk) * NPOS + p0 + pq * 4];
            *(float4*)&Xt[kk][pq * 4] = xv;
        }
        __syncthreads();
        #pragma unroll
        for (int kk = 0; kk < 16; kk++) {
            float4 a  = *(float4*)&Wt[kk][ty * 4];
            float4 bv = *(float4*)&Xt[kk][tx * 4];
            float av[4] = {a.x, a.y, a.z, a.w};
            float bb[4] = {bv.x, bv.y, bv.z, bv.w};
            #pragma unroll
            for (int i = 0; i < 4; i++)
                #pragma unroll
                for (int j = 0; j < 4; j++) acc[i][j] += av[i] * bb[j];
        }
        __syncthreads();
    }

    #pragma unroll
    for (int i = 0; i < 4; i++) {
        int o = o0 + ty * 4 + i;
        int part = o >> 7;
        int oc = o & 127;
        int head = oc >> 5, d = oc & 31;
        float* dst = (part == 0) ? g_q : (part == 1) ? g_k : g_v;
        float sc = (part == 0) ? SCALE : 1.0f;
        size_t base = (((size_t)b * HEADS + head) * NPOS) * DIM_HEAD + d;
        #pragma unroll
        for (int j = 0; j < 4; j++) {
            int pos = p0 + tx * 4 + j;
            dst[base + (size_t)pos * DIM_HEAD] = acc[i][j] * sc;
        }
    }
}

// ---------------------------------------------------------------------------
// Kernel 2: tf32-MMA flash attention.
// Block = 8 warps, Q tile = 128 rows (16/warp). Key tile = 64.
// S = Q K^T via m16n8k8; softmax in C-fragments with quad shuffles;
// P relayout C-frag -> A-frag via warp shuffles (no smem); PV via m16n8k8.
// ---------------------------------------------------------------------------
#define STK 36
#define STV 40

__global__ __launch_bounds__(256) void attn_mma_kernel() {
    __shared__ __align__(16) float Ks[64][STK];
    __shared__ __align__(16) float Vs[64][STV];

    const int bh = blockIdx.y;
    const int q0 = blockIdx.x * 128;
    const int tid = threadIdx.x;
    const int warp = tid >> 5, lane = tid & 31;
    const int g = lane >> 2, tg = lane & 3;  // groupID / thread-in-group

    const float* Qg = g_q + (size_t)bh * NPOS * DIM_HEAD;
    const float* Kg = g_k + (size_t)bh * NPOS * DIM_HEAD;
    const float* Vg = g_v + (size_t)bh * NPOS * DIM_HEAD;

    // Q fragments (A-layout, tf32): rows qrow0, qrow0+8; 4 k-chunks of 8
    const int qrow0 = q0 + warp * 16 + g;
    uint32_t Qf[4][4];
    #pragma unroll
    for (int kt = 0; kt < 4; kt++) {
        int c = kt * 8 + tg;
        Qf[kt][0] = f2tf32(Qg[(size_t)qrow0 * DIM_HEAD + c]);
        Qf[kt][1] = f2tf32(Qg[(size_t)(qrow0 + 8) * DIM_HEAD + c]);
        Qf[kt][2] = f2tf32(Qg[(size_t)qrow0 * DIM_HEAD + c + 4]);
        Qf[kt][3] = f2tf32(Qg[(size_t)(qrow0 + 8) * DIM_HEAD + c + 4]);
    }

    float O[4][4] = {};
    float m0 = -1e30f, m1 = -1e30f, l0 = 0.f, l1 = 0.f;
    const unsigned FULL = 0xffffffffu;

    for (int t = 0; t < NPOS; t += 64) {
        __syncthreads();
        // Cooperative K/V tile load (64x32 each), converted to tf32 bits
        #pragma unroll
        for (int e = 0; e < 2; e++) {
            int idx = tid + e * 256;
            int r = idx >> 3, q4 = (idx & 7) * 4;
            float4 kv = *(const float4*)&Kg[(size_t)(t + r) * DIM_HEAD + q4];
            Ks[r][q4 + 0] = __uint_as_float(f2tf32(kv.x));
            Ks[r][q4 + 1] = __uint_as_float(f2tf32(kv.y));
            Ks[r][q4 + 2] = __uint_as_float(f2tf32(kv.z));
            Ks[r][q4 + 3] = __uint_as_float(f2tf32(kv.w));
            float4 vv = *(const float4*)&Vg[(size_t)(t + r) * DIM_HEAD + q4];
            Vs[r][q4 + 0] = __uint_as_float(f2tf32(vv.x));
            Vs[r][q4 + 1] = __uint_as_float(f2tf32(vv.y));
            Vs[r][q4 + 2] = __uint_as_float(f2tf32(vv.z));
            Vs[r][q4 + 3] = __uint_as_float(f2tf32(vv.w));
        }
        __syncthreads();

        // ---- S = Q K^T : 8 n-tiles (64 keys) x 4 k-chunks
        float S[8][4];
        #pragma unroll
        for (int nt = 0; nt < 8; nt++) {
            S[nt][0] = S[nt][1] = S[nt][2] = S[nt][3] = 0.f;
            const int key = nt * 8 + g;
            #pragma unroll
            for (int kt = 0; kt < 4; kt++) {
                const int d = kt * 8 + tg;
                uint32_t b0 = __float_as_uint(Ks[key][d]);
                uint32_t b1 = __float_as_uint(Ks[key][d + 4]);
                mma_tf32(S[nt], Qf[kt][0], Qf[kt][1], Qf[kt][2], Qf[kt][3], b0, b1);
            }
        }

        // ---- online softmax (rows qrow0 -> {c0,c1}, qrow0+8 -> {c2,c3})
        float rmax0 = -1e30f, rmax1 = -1e30f;
        #pragma unroll
        for (int nt = 0; nt < 8; nt++) {
            rmax0 = fmaxf(rmax0, fmaxf(S[nt][0], S[nt][1]));
            rmax1 = fmaxf(rmax1, fmaxf(S[nt][2], S[nt][3]));
        }
        rmax0 = fmaxf(rmax0, __shfl_xor_sync(FULL, rmax0, 1));
        rmax0 = fmaxf(rmax0, __shfl_xor_sync(FULL, rmax0, 2));
        rmax1 = fmaxf(rmax1, __shfl_xor_sync(FULL, rmax1, 1));
        rmax1 = fmaxf(rmax1, __shfl_xor_sync(FULL, rmax1, 2));

        float mn0 = fmaxf(m0, rmax0), mn1 = fmaxf(m1, rmax1);
        float alpha0 = __expf(m0 - mn0), alpha1 = __expf(m1 - mn1);
        m0 = mn0; m1 = mn1;

        float rs0 = 0.f, rs1 = 0.f;
        #pragma unroll
        for (int nt = 0; nt < 8; nt++) {
            S[nt][0] = __expf(S[nt][0] - mn0);
            S[nt][1] = __expf(S[nt][1] - mn0);
            S[nt][2] = __expf(S[nt][2] - mn1);
            S[nt][3] = __expf(S[nt][3] - mn1);
            rs0 += S[nt][0] + S[nt][1];
            rs1 += S[nt][2] + S[nt][3];
        }
        rs0 += __shfl_xor_sync(FULL, rs0, 1);
        rs0 += __shfl_xor_sync(FULL, rs0, 2);
        rs1 += __shfl_xor_sync(FULL, rs1, 1);
        rs1 += __shfl_xor_sync(FULL, rs1, 2);
        l0 = l0 * alpha0 + rs0;
        l1 = l1 * alpha1 + rs1;

        #pragma unroll
        for (int nt = 0; nt < 4; nt++) {
            O[nt][0] *= alpha0; O[nt][1] *= alpha0;
            O[nt][2] *= alpha1; O[nt][3] *= alpha1;
        }

        // ---- O += P V : relayout P (C-frag -> A-frag) via shuffles per 8-key chunk
        const int srcA = g * 4 + (tg >> 1);
        const int srcB = srcA + 2;
        const bool odd = (tg & 1);
        #pragma unroll
        for (int kt = 0; kt < 8; kt++) {
            uint32_t p0 = f2tf32(S[kt][0]);
            uint32_t p1 = f2tf32(S[kt][1]);
            uint32_t p2 = f2tf32(S[kt][2]);
            uint32_t p3 = f2tf32(S[kt][3]);
            uint32_t x0 = __shfl_sync(FULL, p0, srcA);
            uint32_t x1 = __shfl_sync(FULL, p1, srcA);
            uint32_t a0 = odd ? x1 : x0;
            uint32_t y0 = __shfl_sync(FULL, p2, srcA);
            uint32_t y1 = __shfl_sync(FULL, p3, srcA);
            uint32_t a1 = odd ? y1 : y0;
            uint32_t x2 = __shfl_sync(FULL, p0, srcB);
            uint32_t x3 = __shfl_sync(FULL, p1, srcB);
            uint32_t a2 = odd ? x3 : x2;
            uint32_t y2 = __shfl_sync(FULL, p2, srcB);
            uint32_t y3 = __shfl_sync(FULL, p3, srcB);
            uint32_t a3 = odd ? y3 : y2;

            const int key = kt * 8 + tg;
            #pragma unroll
            for (int nt = 0; nt < 4; nt++) {
                const int d = nt * 8 + g;
                uint32_t b0 = __float_as_uint(Vs[key][d]);
                uint32_t b1 = __float_as_uint(Vs[key + 4][d]);
                mma_tf32(O[nt], a0, a1, a2, a3, b0, b1);
            }
        }
    }

    // ---- epilogue: normalize, write to g_attn[b][pos][head*32 + d]
    const int b = bh >> 2, head = bh & 3;
    const float inv0 = 1.f / l0, inv1 = 1.f / l1;
    #pragma unroll
    for (int nt = 0; nt < 4; nt++) {
        int col = head * 32 + nt * 8 + 2 * tg;
        float2 w0 = make_float2(O[nt][0] * inv0, O[nt][1] * inv0);
        float2 w1 = make_float2(O[nt][2] * inv1, O[nt][3] * inv1);
        *(float2*)&g_attn[((size_t)b * NPOS + qrow0) * HIDDEN + col] = w0;
        *(float2*)&g_attn[((size_t)b * NPOS + qrow0 + 8) * HIDDEN + col] = w1;
    }
}

// ---------------------------------------------------------------------------
// Kernel 3: output projection + bias.
// ---------------------------------------------------------------------------
__global__ __launch_bounds__(256) void proj_kernel(const float* __restrict__ w,
                                                   const float* __restrict__ bias,
                                                   float* __restrict__ y) {
    __shared__ __align__(16) float Wt[16][68];
    __shared__ __align__(16) float Bt[16][68];
    const int b  = blockIdx.z;
    const int o0 = blockIdx.y * 64;
    const int p0 = blockIdx.x * 64;
    const int tid = threadIdx.x;
    const int ty = tid >> 4, tx = tid & 15;

    float acc[4][4] = {};

    for (int k0 = 0; k0 < HIDDEN; k0 += 16) {
        {
            int oo = tid >> 2, kq = tid & 3;
            float4 wv = *(const float4*)&w[(o0 + oo) * HIDDEN + k0 + kq * 4];
            Wt[kq * 4 + 0][oo] = wv.x;
            Wt[kq * 4 + 1][oo] = wv.y;
            Wt[kq * 4 + 2][oo] = wv.z;
            Wt[kq * 4 + 3][oo] = wv.w;
        }
        {
            int pp = tid >> 2, kq = tid & 3;
            float4 av = *(const float4*)&g_attn[((size_t)b * NPOS + p0 + pp) * HIDDEN + k0 + kq * 4];
            Bt[kq * 4 + 0][pp] = av.x;
            Bt[kq * 4 + 1][pp] = av.y;
            Bt[kq * 4 + 2][pp] = av.z;
            Bt[kq * 4 + 3][pp] = av.w;
        }
        __syncthreads();
        #pragma unroll
        for (int kk = 0; kk < 16; kk++) {
            float4 a  = *(float4*)&Wt[kk][ty * 4];
            float4 bv = *(float4*)&Bt[kk][tx * 4];
            float av[4] = {a.x, a.y, a.z, a.w};
            float bb[4] = {bv.x, bv.y, bv.z, bv.w};
            #pragma unroll
            for (int i = 0; i < 4; i++)
                #pragma unroll
                for (int j = 0; j < 4; j++) acc[i][j] += av[i] * bb[j];
        }
        __syncthreads();
    }

    #pragma unroll
    for (int i = 0; i < 4; i++) {
        int o = o0 + ty * 4 + i;
        float bb = bias[o];
        #pragma unroll
        for (int j = 0; j < 4; j++) {
            int pos = p0 + tx * 4 + j;
            y[((size_t)b * CDIM + o) * NPOS + pos] = acc[i][j] + bb;
        }
    }
}

// ---------------------------------------------------------------------------
extern "C" void kernel_launch(void* const* d_in, const int* in_sizes, int n_in,
                              void* d_out, int out_size) {
    const float* x     = (const float*)d_in[0];
    const float* w_qkv = (const float*)d_in[1];
    const float* w_out = (const float*)d_in[2];
    const float* b_out = (const float*)d_in[3];
    float* y = (float*)d_out;

    qkv_kernel<<<dim3(NPOS / 64, 384 / 64, BATCH), 256>>>(x, w_qkv);
    attn_mma_kernel<<<dim3(NPOS / 128, BATCH * HEADS), 256>>>();
    proj_kernel<<<dim3(NPOS / 64, CDIM / 64, BATCH), 256>>>(w_out, b_out, y);
}